// round 1
// baseline (speedup 1.0000x reference)
#include <cuda_runtime.h>

// Problem constants (from reference: B=64, C=256, T=2048, fp32)
#define BATCH 64
#define CDIM  256
#define TDIM  2048

// GEMM tiling
#define BM 128
#define BN 128
#define BK 8
#define TM 8
#define TN 8
#define PAD 4   // keeps 16B alignment of smem rows (132 floats = 528B, 528 % 16 == 0)

// Scratch for per-(b,c) means — device global, no allocation.
__device__ float g_mean[BATCH * CDIM];

// ---------------------------------------------------------------------------
// Kernel 1: one warp per (b, c) row — mean over T=2048 floats.
// ---------------------------------------------------------------------------
__global__ void mean_kernel(const float* __restrict__ X) {
    int warp = (blockIdx.x * blockDim.x + threadIdx.x) >> 5;
    int lane = threadIdx.x & 31;
    if (warp >= BATCH * CDIM) return;

    const float4* row = reinterpret_cast<const float4*>(X + (size_t)warp * TDIM);
    float s = 0.0f;
#pragma unroll 4
    for (int i = lane; i < TDIM / 4; i += 32) {
        float4 v = row[i];
        s += (v.x + v.y) + (v.z + v.w);
    }
#pragma unroll
    for (int off = 16; off > 0; off >>= 1)
        s += __shfl_xor_sync(0xffffffffu, s, off);
    if (lane == 0)
        g_mean[warp] = s * (1.0f / TDIM);
}

// ---------------------------------------------------------------------------
// Kernel 2: per-batch Gram tiles. blockIdx.x selects which 128x128 tile of
// the 256x256 output: 0 -> (0,0), 1 -> (1,1), 2 -> (0,1) (mirrored to (1,0)).
// cov[c,d] = (sum_t X[c,t]*X[d,t]) / T - mean[c]*mean[d]
// ---------------------------------------------------------------------------
__global__ void __launch_bounds__(256, 2)
cov_kernel(const float* __restrict__ X, float* __restrict__ out) {
    __shared__ float As[BK][BM + PAD];
    __shared__ float Bs[BK][BN + PAD];

    const int b    = blockIdx.y;
    const int tile = blockIdx.x;           // 0,1,2
    const int tr   = (tile == 1) ? 1 : 0;
    const int tc   = (tile >= 1) ? 1 : 0;
    const int row0 = tr * BM;
    const int col0 = tc * BN;

    const float* A = X + (size_t)b * CDIM * TDIM;

    const int tid  = threadIdx.x;
    const int tx   = tid & 15;             // 0..15  (cols)
    const int ty   = tid >> 4;             // 0..15  (rows)

    // smem-fill mapping: each thread loads one float4 per tile
    const int lrow = tid >> 1;             // 0..127
    const int lcol = (tid & 1) * 4;        // 0 or 4

    const float* Aptr = A + (size_t)(row0 + lrow) * TDIM + lcol;
    const float* Bptr = A + (size_t)(col0 + lrow) * TDIM + lcol;

    float acc[TM][TN];
#pragma unroll
    for (int i = 0; i < TM; i++)
#pragma unroll
        for (int j = 0; j < TN; j++) acc[i][j] = 0.0f;

    // Prime the register prefetch for kt = 0
    float4 aReg = *reinterpret_cast<const float4*>(Aptr);
    float4 bReg = *reinterpret_cast<const float4*>(Bptr);

    for (int kt = 0; kt < TDIM; kt += BK) {
        // Commit prefetched regs to smem (transposed: [k][row])
        As[lcol + 0][lrow] = aReg.x;
        As[lcol + 1][lrow] = aReg.y;
        As[lcol + 2][lrow] = aReg.z;
        As[lcol + 3][lrow] = aReg.w;
        Bs[lcol + 0][lrow] = bReg.x;
        Bs[lcol + 1][lrow] = bReg.y;
        Bs[lcol + 2][lrow] = bReg.z;
        Bs[lcol + 3][lrow] = bReg.w;
        __syncthreads();

        // Prefetch next K-slab while computing this one
        if (kt + BK < TDIM) {
            aReg = *reinterpret_cast<const float4*>(Aptr + kt + BK);
            bReg = *reinterpret_cast<const float4*>(Bptr + kt + BK);
        }

#pragma unroll
        for (int k = 0; k < BK; k++) {
            float af[TM], bf[TN];
            float4 a0 = *reinterpret_cast<const float4*>(&As[k][ty * TM]);
            float4 a1 = *reinterpret_cast<const float4*>(&As[k][ty * TM + 4]);
            float4 b0 = *reinterpret_cast<const float4*>(&Bs[k][tx * TN]);
            float4 b1 = *reinterpret_cast<const float4*>(&Bs[k][tx * TN + 4]);
            af[0] = a0.x; af[1] = a0.y; af[2] = a0.z; af[3] = a0.w;
            af[4] = a1.x; af[5] = a1.y; af[6] = a1.z; af[7] = a1.w;
            bf[0] = b0.x; bf[1] = b0.y; bf[2] = b0.z; bf[3] = b0.w;
            bf[4] = b1.x; bf[5] = b1.y; bf[6] = b1.z; bf[7] = b1.w;
#pragma unroll
            for (int i = 0; i < TM; i++)
#pragma unroll
                for (int j = 0; j < TN; j++)
                    acc[i][j] = fmaf(af[i], bf[j], acc[i][j]);
        }
        __syncthreads();
    }

    // Epilogue: cov = acc/T - m_r * m_c ; mirror the off-diagonal tile.
    const float invT = 1.0f / TDIM;
    const float* mb = g_mean + b * CDIM;
    float mr[TM], mc[TN];
#pragma unroll
    for (int i = 0; i < TM; i++) mr[i] = mb[row0 + ty * TM + i];
#pragma unroll
    for (int j = 0; j < TN; j++) mc[j] = mb[col0 + tx * TN + j];

    float* O = out + (size_t)b * CDIM * CDIM;
#pragma unroll
    for (int i = 0; i < TM; i++) {
        const int r = row0 + ty * TM + i;
        float v[TN];
#pragma unroll
        for (int j = 0; j < TN; j++)
            v[j] = acc[i][j] * invT - mr[i] * mc[j];

        // vectorized main writes
        float4* dst = reinterpret_cast<float4*>(&O[(size_t)r * CDIM + col0 + tx * TN]);
        dst[0] = make_float4(v[0], v[1], v[2], v[3]);
        dst[1] = make_float4(v[4], v[5], v[6], v[7]);

        if (tile == 2) {
            // mirror into (1,0) block
#pragma unroll
            for (int j = 0; j < TN; j++) {
                const int c = col0 + tx * TN + j;
                O[(size_t)c * CDIM + r] = v[j];
            }
        }
    }
}

// ---------------------------------------------------------------------------
extern "C" void kernel_launch(void* const* d_in, const int* in_sizes, int n_in,
                              void* d_out, int out_size) {
    const float* X  = reinterpret_cast<const float*>(d_in[0]);
    float*       O  = reinterpret_cast<float*>(d_out);

    // Means: 64*256 rows, one warp each -> 16384 warps -> 2048 blocks of 256
    mean_kernel<<<(BATCH * CDIM * 32) / 256, 256>>>(X);

    // Gram tiles: 3 tiles per batch (upper-tri block structure), 64 batches
    dim3 grid(3, BATCH);
    cov_kernel<<<grid, 256>>>(X, O);
}

// round 2
// speedup vs baseline: 1.1102x; 1.1102x over previous
#include <cuda_runtime.h>

// Problem constants: B=64, C=256, T=2048, fp32
#define BATCH 64
#define CDIM  256
#define TDIM  2048
#define KSPLIT 4
#define KLEN  (TDIM / KSPLIT)   // 512 per split

// GEMM tiling
#define BM 128
#define BN 128
#define BK 8
#define TM 8
#define TN 8
#define PAD 4

__device__ float g_mean[BATCH * CDIM];

// ---------------------------------------------------------------------------
// packed-f32x2 helpers (FFMA2: 2 MACs per fma-pipe issue; PTX-only on sm_103a)
// ---------------------------------------------------------------------------
__device__ __forceinline__ unsigned long long dup2(float v) {
    unsigned long long r;
    asm("mov.b64 %0, {%1, %1};" : "=l"(r) : "f"(v));
    return r;
}
__device__ __forceinline__ unsigned long long pack2(float lo, float hi) {
    unsigned long long r;
    asm("mov.b64 %0, {%1, %2};" : "=l"(r) : "f"(lo), "f"(hi));
    return r;
}
__device__ __forceinline__ void ffma2(unsigned long long& d,
                                      unsigned long long a,
                                      unsigned long long b) {
    asm("fma.rn.f32x2 %0, %1, %2, %0;" : "+l"(d) : "l"(a), "l"(b));
}
__device__ __forceinline__ void unpack2(unsigned long long v, float& lo, float& hi) {
    asm("mov.b64 {%0, %1}, %2;" : "=f"(lo), "=f"(hi) : "l"(v));
}

// ---------------------------------------------------------------------------
// Kernel 1: one warp per (b, c) row — mean over T.
// ---------------------------------------------------------------------------
__global__ void mean_kernel(const float* __restrict__ X) {
    int warp = (blockIdx.x * blockDim.x + threadIdx.x) >> 5;
    int lane = threadIdx.x & 31;
    if (warp >= BATCH * CDIM) return;

    const float4* row = reinterpret_cast<const float4*>(X + (size_t)warp * TDIM);
    float s = 0.0f;
#pragma unroll 4
    for (int i = lane; i < TDIM / 4; i += 32) {
        float4 v = row[i];
        s += (v.x + v.y) + (v.z + v.w);
    }
#pragma unroll
    for (int off = 16; off > 0; off >>= 1)
        s += __shfl_xor_sync(0xffffffffu, s, off);
    if (lane == 0)
        g_mean[warp] = s * (1.0f / TDIM);
}

// ---------------------------------------------------------------------------
// Kernel 2: initialize out[b][c][d] = -m[b][c]*m[b][d]. Split-K gram CTAs
// then red.add their acc/T partials on top.
// grid = BATCH*CDIM blocks of 64 threads; each block fills one 256-float row.
// ---------------------------------------------------------------------------
__global__ void init_kernel(float* __restrict__ out) {
    int b = blockIdx.x >> 8;
    int c = blockIdx.x & 255;
    const float* m = g_mean + b * CDIM;
    float mc = -m[c];
    float4 md = reinterpret_cast<const float4*>(m)[threadIdx.x];
    float* row = out + ((size_t)b * CDIM + c) * CDIM;
    reinterpret_cast<float4*>(row)[threadIdx.x] =
        make_float4(mc * md.x, mc * md.y, mc * md.z, mc * md.w);
}

// ---------------------------------------------------------------------------
// Kernel 3: split-K gram tiles with packed FFMA2.
// blockIdx: x = tile (0:(0,0), 1:(1,1), 2:(0,1)+mirror), y = batch, z = ksplit
// Accumulates (1/T)*sum_{t in split} X[c,t]X[d,t] into out via red.add.f32.
// ---------------------------------------------------------------------------
__global__ void __launch_bounds__(256, 2)
cov_kernel(const float* __restrict__ X, float* __restrict__ out) {
    __shared__ float As[BK][BM + PAD];
    __shared__ float Bs[BK][BN + PAD];

    const int b    = blockIdx.y;
    const int tile = blockIdx.x;
    const int ks   = blockIdx.z;
    const int tr   = (tile == 1) ? 1 : 0;
    const int tc   = (tile >= 1) ? 1 : 0;
    const int row0 = tr * BM;
    const int col0 = tc * BN;
    const int k0   = ks * KLEN;

    const float* A = X + (size_t)b * CDIM * TDIM;

    const int tid  = threadIdx.x;
    const int tx   = tid & 15;
    const int ty   = tid >> 4;

    const int lrow = tid >> 1;
    const int lcol = (tid & 1) * 4;

    const float* Aptr = A + (size_t)(row0 + lrow) * TDIM + k0 + lcol;
    const float* Bptr = A + (size_t)(col0 + lrow) * TDIM + k0 + lcol;

    // 8x8 fp32 accumulators packed as 8x4 f32x2 pairs
    unsigned long long acc2[TM][TN / 2];
#pragma unroll
    for (int i = 0; i < TM; i++)
#pragma unroll
        for (int j = 0; j < TN / 2; j++) acc2[i][j] = 0ull;

    float4 aReg = *reinterpret_cast<const float4*>(Aptr);
    float4 bReg = *reinterpret_cast<const float4*>(Bptr);

    for (int kt = 0; kt < KLEN; kt += BK) {
        As[lcol + 0][lrow] = aReg.x;
        As[lcol + 1][lrow] = aReg.y;
        As[lcol + 2][lrow] = aReg.z;
        As[lcol + 3][lrow] = aReg.w;
        Bs[lcol + 0][lrow] = bReg.x;
        Bs[lcol + 1][lrow] = bReg.y;
        Bs[lcol + 2][lrow] = bReg.z;
        Bs[lcol + 3][lrow] = bReg.w;
        __syncthreads();

        if (kt + BK < KLEN) {
            aReg = *reinterpret_cast<const float4*>(Aptr + kt + BK);
            bReg = *reinterpret_cast<const float4*>(Bptr + kt + BK);
        }

#pragma unroll
        for (int k = 0; k < BK; k++) {
            float4 a0 = *reinterpret_cast<const float4*>(&As[k][ty * TM]);
            float4 a1 = *reinterpret_cast<const float4*>(&As[k][ty * TM + 4]);
            float4 b0 = *reinterpret_cast<const float4*>(&Bs[k][tx * TN]);
            float4 b1 = *reinterpret_cast<const float4*>(&Bs[k][tx * TN + 4]);

            unsigned long long a2[TM];
            a2[0] = dup2(a0.x); a2[1] = dup2(a0.y);
            a2[2] = dup2(a0.z); a2[3] = dup2(a0.w);
            a2[4] = dup2(a1.x); a2[5] = dup2(a1.y);
            a2[6] = dup2(a1.z); a2[7] = dup2(a1.w);

            unsigned long long b2[TN / 2];
            b2[0] = pack2(b0.x, b0.y);
            b2[1] = pack2(b0.z, b0.w);
            b2[2] = pack2(b1.x, b1.y);
            b2[3] = pack2(b1.z, b1.w);

#pragma unroll
            for (int i = 0; i < TM; i++)
#pragma unroll
                for (int j = 0; j < TN / 2; j++)
                    ffma2(acc2[i][j], a2[i], b2[j]);
        }
        __syncthreads();
    }

    // Epilogue: red.add acc/T into out (pre-initialized to -m*m^T).
    const float invT = 1.0f / TDIM;
    float* O = out + (size_t)b * CDIM * CDIM;

#pragma unroll
    for (int i = 0; i < TM; i++) {
        const int r = row0 + ty * TM + i;
        float v[TN];
#pragma unroll
        for (int j = 0; j < TN / 2; j++) {
            float lo, hi;
            unpack2(acc2[i][j], lo, hi);
            v[2 * j]     = lo * invT;
            v[2 * j + 1] = hi * invT;
        }
        float* dst = &O[(size_t)r * CDIM + col0 + tx * TN];
#pragma unroll
        for (int j = 0; j < TN; j++)
            atomicAdd(dst + j, v[j]);

        if (tile == 2) {
#pragma unroll
            for (int j = 0; j < TN; j++) {
                const int c = col0 + tx * TN + j;
                atomicAdd(&O[(size_t)c * CDIM + r], v[j]);
            }
        }
    }
}

// ---------------------------------------------------------------------------
extern "C" void kernel_launch(void* const* d_in, const int* in_sizes, int n_in,
                              void* d_out, int out_size) {
    const float* X = reinterpret_cast<const float*>(d_in[0]);
    float*       O = reinterpret_cast<float*>(d_out);

    mean_kernel<<<(BATCH * CDIM * 32) / 256, 256>>>(X);
    init_kernel<<<BATCH * CDIM, 64>>>(O);

    dim3 grid(3, BATCH, KSPLIT);
    cov_kernel<<<grid, 256>>>(X, O);
}

// round 4
// speedup vs baseline: 3.1496x; 2.8370x over previous
#include <cuda_runtime.h>
#include <cstdint>

#define BATCH 64
#define CDIM  256
#define TDIM  2048

// CTA tile: M=128 (half of C), N=256 (all of C), K=2048
#define BK      16
#define NSTEPS  (TDIM / BK)          // 128
#define NSTAGES 4

#define STRIDE  20                   // floats per smem row (80B): conflict-free frags
#define A_BYTES (128 * STRIDE * 4)   // 10240
#define B_BYTES (256 * STRIDE * 4)   // 20480
#define STAGE_BYTES (A_BYTES + B_BYTES)          // 30720
#define SMEM_BUF 1024                              // means in [0,1024)
#define SMEM_TOTAL (SMEM_BUF + NSTAGES * STAGE_BYTES)  // 123904

__device__ float g_mean[BATCH * CDIM];

__device__ __forceinline__ uint32_t smem_u32(const void* p) {
    uint32_t a;
    asm("{ .reg .u64 t; cvta.to.shared.u64 t, %1; cvt.u32.u64 %0, t; }"
        : "=r"(a) : "l"(p));
    return a;
}
__device__ __forceinline__ void cpasync16(uint32_t dst, const void* src) {
    asm volatile("cp.async.cg.shared.global [%0], [%1], 16;"
                 :: "r"(dst), "l"(src) : "memory");
}
__device__ __forceinline__ void mma_tf32(float* c, const uint32_t* a, const uint32_t* b) {
    asm volatile(
        "mma.sync.aligned.m16n8k8.row.col.f32.tf32.tf32.f32 "
        "{%0,%1,%2,%3}, {%4,%5,%6,%7}, {%8,%9}, {%0,%1,%2,%3};"
        : "+f"(c[0]), "+f"(c[1]), "+f"(c[2]), "+f"(c[3])
        : "r"(a[0]), "r"(a[1]), "r"(a[2]), "r"(a[3]), "r"(b[0]), "r"(b[1]));
}

// ---------------------------------------------------------------------------
// mean kernel: one warp per (b, c) row
// ---------------------------------------------------------------------------
__global__ void mean_kernel(const float* __restrict__ X) {
    int warp = (blockIdx.x * blockDim.x + threadIdx.x) >> 5;
    int lane = threadIdx.x & 31;
    if (warp >= BATCH * CDIM) return;
    const float4* row = reinterpret_cast<const float4*>(X + (size_t)warp * TDIM);
    float s = 0.0f;
#pragma unroll 4
    for (int i = lane; i < TDIM / 4; i += 32) {
        float4 v = row[i];
        s += (v.x + v.y) + (v.z + v.w);
    }
#pragma unroll
    for (int off = 16; off > 0; off >>= 1)
        s += __shfl_xor_sync(0xffffffffu, s, off);
    if (lane == 0) g_mean[warp] = s * (1.0f / TDIM);
}

// ---------------------------------------------------------------------------
// HMMA tf32 gram kernel. 128 CTAs: blockIdx.x = b*2 + mhalf.
// D[128 x 256] per CTA. 8 warps in 2x4, 64x64 warp tiles.
// cov = D/T - m*m^T applied in epilogue.
// ---------------------------------------------------------------------------
extern __shared__ char dyn_smem[];

__global__ void __launch_bounds__(256)
cov_mma_kernel(const float* __restrict__ X, float* __restrict__ out) {
    const int b     = blockIdx.x >> 1;
    const int row0  = (blockIdx.x & 1) * 128;
    const int tid   = threadIdx.x;
    const int wid   = tid >> 5;
    const int lane  = tid & 31;
    const int g     = lane >> 2;        // group id (0..7)
    const int tig   = lane & 3;         // thread in group
    const int wm    = wid >> 2;         // 0..1 (M)
    const int wn    = wid & 3;          // 0..3 (N)

    const uint32_t smem_base = smem_u32(dyn_smem);
    float* sm_mean = reinterpret_cast<float*>(dyn_smem);

    // means into smem
    sm_mean[tid] = g_mean[b * CDIM + tid];

    // --- loader mapping: 6 x 16B cp.async per thread per stage ---
    const float* Xb = X + (size_t)b * CDIM * TDIM;
    const char* src[6];
    uint32_t    dstoff[6];   // offset within a stage buffer
#pragma unroll
    for (int u = 0; u < 6; u++) {
        int idx = tid + u * 256;
        int row, ch;
        uint32_t base;
        int grow;
        if (u < 2) { row = idx >> 2;         ch = idx & 3; base = 0;       grow = row0 + row; }
        else       { row = (idx - 512) >> 2; ch = idx & 3; base = A_BYTES; grow = row; }
        dstoff[u] = base + (uint32_t)(row * (STRIDE * 4) + ch * 16);
        src[u] = reinterpret_cast<const char*>(Xb + (size_t)grow * TDIM + ch * 4);
    }

    // --- prologue: stages 0..2 ---
#pragma unroll
    for (int p = 0; p < NSTAGES - 1; p++) {
        uint32_t sb = smem_base + SMEM_BUF + p * STAGE_BYTES;
#pragma unroll
        for (int u = 0; u < 6; u++)
            cpasync16(sb + dstoff[u], src[u] + (size_t)p * (BK * 4));
        asm volatile("cp.async.commit_group;" ::: "memory");
    }

    // fragment base offsets (in floats, within stage)
    const int aBase = (wm * 64 + g) * STRIDE + tig;
    const int bBase = (wn * 64 + g) * STRIDE + tig;

    float acc[4][8][4];
#pragma unroll
    for (int i = 0; i < 4; i++)
#pragma unroll
        for (int j = 0; j < 8; j++)
#pragma unroll
            for (int q = 0; q < 4; q++) acc[i][j][q] = 0.0f;

    for (int s = 0; s < NSTEPS; s++) {
        if (s + NSTAGES - 1 < NSTEPS)
            asm volatile("cp.async.wait_group 2;" ::: "memory");
        else
            asm volatile("cp.async.wait_group 0;" ::: "memory");
        __syncthreads();

        const char* stage = dyn_smem + SMEM_BUF + (s & (NSTAGES - 1)) * STAGE_BYTES;
        const uint32_t* As = reinterpret_cast<const uint32_t*>(stage);
        const uint32_t* Bs = reinterpret_cast<const uint32_t*>(stage + A_BYTES);

#pragma unroll
        for (int kk = 0; kk < 2; kk++) {
            const int ko = kk * 8;
            uint32_t a[4][4], bf[8][2];
#pragma unroll
            for (int i = 0; i < 4; i++) {
                const int o = aBase + i * (16 * STRIDE) + ko;
                a[i][0] = As[o]                   + 0x1000u;
                a[i][1] = As[o + 8 * STRIDE]      + 0x1000u;
                a[i][2] = As[o + 4]               + 0x1000u;
                a[i][3] = As[o + 8 * STRIDE + 4]  + 0x1000u;
            }
#pragma unroll
            for (int j = 0; j < 8; j++) {
                const int o = bBase + j * (8 * STRIDE) + ko;
                bf[j][0] = Bs[o]     + 0x1000u;
                bf[j][1] = Bs[o + 4] + 0x1000u;
            }
#pragma unroll
            for (int i = 0; i < 4; i++)
#pragma unroll
                for (int j = 0; j < 8; j++)
                    mma_tf32(acc[i][j], a[i], bf[j]);
        }

        // prefetch stage s+3 into slot (s+3)&3 (computed in iter s-1; all
        // warps passed this iter's barrier only after finishing it)
        if (s + NSTAGES - 1 < NSTEPS) {
            const int ps = s + NSTAGES - 1;
            uint32_t sb = smem_base + SMEM_BUF + (ps & (NSTAGES - 1)) * STAGE_BYTES;
#pragma unroll
            for (int u = 0; u < 6; u++)
                cpasync16(sb + dstoff[u], src[u] + (size_t)ps * (BK * 4));
            asm volatile("cp.async.commit_group;" ::: "memory");
        }
    }

    // --- epilogue: cov = acc/T - m_r*m_c ---
    const float invT = 1.0f / TDIM;
    float* outB = out + (size_t)b * CDIM * CDIM;

#pragma unroll
    for (int i = 0; i < 4; i++) {
        const int r0 = row0 + wm * 64 + i * 16 + g;   // global row in batch
        const int r1 = r0 + 8;
        const float mr0 = sm_mean[r0];
        const float mr1 = sm_mean[r1];
#pragma unroll
        for (int j = 0; j < 8; j++) {
            const int c = wn * 64 + j * 8 + 2 * tig;
            const float mc0 = sm_mean[c];
            const float mc1 = sm_mean[c + 1];
            float2 v0, v1;
            v0.x = acc[i][j][0] * invT - mr0 * mc0;
            v0.y = acc[i][j][1] * invT - mr0 * mc1;
            v1.x = acc[i][j][2] * invT - mr1 * mc0;
            v1.y = acc[i][j][3] * invT - mr1 * mc1;
            *reinterpret_cast<float2*>(outB + (size_t)r0 * CDIM + c) = v0;
            *reinterpret_cast<float2*>(outB + (size_t)r1 * CDIM + c) = v1;
        }
    }
}

// ---------------------------------------------------------------------------
extern "C" void kernel_launch(void* const* d_in, const int* in_sizes, int n_in,
                              void* d_out, int out_size) {
    const float* X = reinterpret_cast<const float*>(d_in[0]);
    float*       O = reinterpret_cast<float*>(d_out);

    cudaFuncSetAttribute(cov_mma_kernel,
                         cudaFuncAttributeMaxDynamicSharedMemorySize,
                         SMEM_TOTAL);

    mean_kernel<<<(BATCH * CDIM * 32) / 256, 256>>>(X);
    cov_mma_kernel<<<BATCH * 2, 256, SMEM_TOTAL>>>(X, O);
}

// round 5
// speedup vs baseline: 4.2717x; 1.3563x over previous
#include <cuda_runtime.h>
#include <cuda_fp16.h>
#include <cstdint>

#define BATCH 64
#define CDIM  256
#define TDIM  2048

#define BK      32                    // k per stage (halves)
#define NSTEPS  (TDIM / BK)           // 64
#define NSTAGES 4

#define ROWB    80                    // bytes per smem row (64 data + 16 pad)
#define A_BYTES (128 * ROWB)          // 10240
#define B_BYTES (256 * ROWB)          // 20480
#define STAGE_BYTES (A_BYTES + B_BYTES)            // 30720
#define SMEM_BUF 1024                               // means in [0,1024)
#define SMEM_TOTAL (SMEM_BUF + NSTAGES * STAGE_BYTES)   // 123904

__device__ float  g_mean[BATCH * CDIM];
__device__ __half g_xh[(size_t)BATCH * CDIM * TDIM];   // 64 MB fp16 scratch

__device__ __forceinline__ uint32_t smem_u32(const void* p) {
    uint32_t a;
    asm("{ .reg .u64 t; cvta.to.shared.u64 t, %1; cvt.u32.u64 %0, t; }"
        : "=r"(a) : "l"(p));
    return a;
}
__device__ __forceinline__ void cpasync16(uint32_t dst, const void* src) {
    asm volatile("cp.async.cg.shared.global [%0], [%1], 16;"
                 :: "r"(dst), "l"(src) : "memory");
}
__device__ __forceinline__ void ldsm_x4(uint32_t* r, uint32_t addr) {
    asm volatile("ldmatrix.sync.aligned.m8n8.x4.shared.b16 {%0,%1,%2,%3}, [%4];"
                 : "=r"(r[0]), "=r"(r[1]), "=r"(r[2]), "=r"(r[3]) : "r"(addr));
}
__device__ __forceinline__ void mma_f16(float* c, const uint32_t* a,
                                        uint32_t b0, uint32_t b1) {
    asm volatile(
        "mma.sync.aligned.m16n8k16.row.col.f32.f16.f16.f32 "
        "{%0,%1,%2,%3}, {%4,%5,%6,%7}, {%8,%9}, {%0,%1,%2,%3};"
        : "+f"(c[0]), "+f"(c[1]), "+f"(c[2]), "+f"(c[3])
        : "r"(a[0]), "r"(a[1]), "r"(a[2]), "r"(a[3]), "r"(b0), "r"(b1));
}

// ---------------------------------------------------------------------------
// Kernel 1: fused mean + fp16 convert. One warp per (b,c) row.
// ---------------------------------------------------------------------------
__global__ void mean_convert_kernel(const float* __restrict__ X) {
    int warp = (blockIdx.x * blockDim.x + threadIdx.x) >> 5;
    int lane = threadIdx.x & 31;
    if (warp >= BATCH * CDIM) return;

    const float4* row = reinterpret_cast<const float4*>(X + (size_t)warp * TDIM);
    uint2* dst = reinterpret_cast<uint2*>(g_xh + (size_t)warp * TDIM);

    float s = 0.0f;
#pragma unroll
    for (int i = lane; i < TDIM / 4; i += 32) {
        float4 v = row[i];
        s += (v.x + v.y) + (v.z + v.w);
        __half2 h01 = __floats2half2_rn(v.x, v.y);
        __half2 h23 = __floats2half2_rn(v.z, v.w);
        uint2 o;
        o.x = reinterpret_cast<uint32_t&>(h01);
        o.y = reinterpret_cast<uint32_t&>(h23);
        dst[i] = o;
    }
#pragma unroll
    for (int off = 16; off > 0; off >>= 1)
        s += __shfl_xor_sync(0xffffffffu, s, off);
    if (lane == 0) g_mean[warp] = s * (1.0f / TDIM);
}

// ---------------------------------------------------------------------------
// Kernel 2: fp16 HMMA gram. 128 CTAs: blockIdx.x = b*2 + mhalf.
// D[128 x 256] per CTA, 8 warps (2x4), warp tile 64x64, m16n8k16.
// ---------------------------------------------------------------------------
extern __shared__ char dyn_smem[];

__global__ void __launch_bounds__(256)
cov_mma_kernel(float* __restrict__ out) {
    const int b    = blockIdx.x >> 1;
    const int row0 = (blockIdx.x & 1) * 128;
    const int tid  = threadIdx.x;
    const int wid  = tid >> 5;
    const int lane = tid & 31;
    const int g    = lane >> 2;
    const int tig  = lane & 3;
    const int wm   = wid >> 2;         // 0..1
    const int wn   = wid & 3;          // 0..3

    const uint32_t smem_base = smem_u32(dyn_smem);
    float* sm_mean = reinterpret_cast<float*>(dyn_smem);
    sm_mean[tid] = g_mean[b * CDIM + tid];

    // --- loader mapping: 6 x 16B cp.async per thread per stage ---
    const __half* Xb = g_xh + (size_t)b * CDIM * TDIM;
    const char* src[6];
    uint32_t    dstoff[6];
#pragma unroll
    for (int u = 0; u < 6; u++) {
        int idx = tid + u * 256;
        int row, ch;
        uint32_t base;
        int grow;
        if (u < 2) { row = idx >> 2;         ch = idx & 3; base = 0;       grow = row0 + row; }
        else       { row = (idx - 512) >> 2; ch = idx & 3; base = A_BYTES; grow = row; }
        dstoff[u] = base + (uint32_t)(row * ROWB + ch * 16);
        src[u] = reinterpret_cast<const char*>(Xb + (size_t)grow * TDIM + ch * 8);
    }

    // --- prologue: stages 0..2 ---
#pragma unroll
    for (int p = 0; p < NSTAGES - 1; p++) {
        uint32_t sb = smem_base + SMEM_BUF + p * STAGE_BYTES;
#pragma unroll
        for (int u = 0; u < 6; u++)
            cpasync16(sb + dstoff[u], src[u] + (size_t)p * (BK * 2));
        asm volatile("cp.async.commit_group;" ::: "memory");
    }

    // --- per-warp ldmatrix base addresses (within a stage buffer) ---
    // addr(L) = (base_row + (L&15))*ROWB + (L>>4)*16  [+ kk*32]
    uint32_t aoff[4], boff[4];
#pragma unroll
    for (int i = 0; i < 4; i++)
        aoff[i] = (uint32_t)((wm * 64 + i * 16 + (lane & 15)) * ROWB + (lane >> 4) * 16);
#pragma unroll
    for (int jp = 0; jp < 4; jp++)
        boff[jp] = A_BYTES +
                   (uint32_t)((wn * 64 + jp * 16 + (lane & 15)) * ROWB + (lane >> 4) * 16);

    float acc[4][8][4];
#pragma unroll
    for (int i = 0; i < 4; i++)
#pragma unroll
        for (int j = 0; j < 8; j++)
#pragma unroll
            for (int q = 0; q < 4; q++) acc[i][j][q] = 0.0f;

    for (int s = 0; s < NSTEPS; s++) {
        if (s < NSTEPS - (NSTAGES - 1))
            asm volatile("cp.async.wait_group 2;" ::: "memory");
        else
            asm volatile("cp.async.wait_group 0;" ::: "memory");
        __syncthreads();

        const uint32_t st = smem_base + SMEM_BUF + (s & (NSTAGES - 1)) * STAGE_BYTES;

        // prefetch stage s+3 (slot was fully consumed in iteration s-1)
        if (s + NSTAGES - 1 < NSTEPS) {
            const int ps = s + NSTAGES - 1;
            uint32_t sb = smem_base + SMEM_BUF + (ps & (NSTAGES - 1)) * STAGE_BYTES;
#pragma unroll
            for (int u = 0; u < 6; u++)
                cpasync16(sb + dstoff[u], src[u] + (size_t)ps * (BK * 2));
            asm volatile("cp.async.commit_group;" ::: "memory");
        }

#pragma unroll
        for (int kk = 0; kk < 2; kk++) {
            const uint32_t ko = st + kk * 32;       // 16 halves = 32B
            uint32_t a[4][4], br[4][4];
#pragma unroll
            for (int i = 0; i < 4; i++) ldsm_x4(a[i], ko + aoff[i]);
#pragma unroll
            for (int jp = 0; jp < 4; jp++) ldsm_x4(br[jp], ko + boff[jp]);
#pragma unroll
            for (int i = 0; i < 4; i++)
#pragma unroll
                for (int jp = 0; jp < 4; jp++) {
                    mma_f16(acc[i][2 * jp],     a[i], br[jp][0], br[jp][2]);
                    mma_f16(acc[i][2 * jp + 1], a[i], br[jp][1], br[jp][3]);
                }
        }
    }

    // --- epilogue: cov = acc/T - m_r*m_c ---
    const float invT = 1.0f / TDIM;
    float* outB = out + (size_t)b * CDIM * CDIM;

#pragma unroll
    for (int i = 0; i < 4; i++) {
        const int r0 = row0 + wm * 64 + i * 16 + g;
        const int r1 = r0 + 8;
        const float mr0 = sm_mean[r0];
        const float mr1 = sm_mean[r1];
#pragma unroll
        for (int j = 0; j < 8; j++) {
            const int c = wn * 64 + j * 8 + 2 * tig;
            const float mc0 = sm_mean[c];
            const float mc1 = sm_mean[c + 1];
            float2 v0, v1;
            v0.x = acc[i][j][0] * invT - mr0 * mc0;
            v0.y = acc[i][j][1] * invT - mr0 * mc1;
            v1.x = acc[i][j][2] * invT - mr1 * mc0;
            v1.y = acc[i][j][3] * invT - mr1 * mc1;
            *reinterpret_cast<float2*>(outB + (size_t)r0 * CDIM + c) = v0;
            *reinterpret_cast<float2*>(outB + (size_t)r1 * CDIM + c) = v1;
        }
    }
}

// ---------------------------------------------------------------------------
extern "C" void kernel_launch(void* const* d_in, const int* in_sizes, int n_in,
                              void* d_out, int out_size) {
    const float* X = reinterpret_cast<const float*>(d_in[0]);
    float*       O = reinterpret_cast<float*>(d_out);

    cudaFuncSetAttribute(cov_mma_kernel,
                         cudaFuncAttributeMaxDynamicSharedMemorySize,
                         SMEM_TOTAL);

    mean_convert_kernel<<<(BATCH * CDIM * 32) / 256, 256>>>(X);
    cov_mma_kernel<<<BATCH * 2, 256, SMEM_TOTAL>>>(O);
}

// round 6
// speedup vs baseline: 4.2729x; 1.0003x over previous
#include <cuda_runtime.h>
#include <cuda_fp16.h>
#include <cstdint>

#define BATCH 64
#define CDIM  256
#define TDIM  2048

#define BK      32                    // k per stage (halves)
#define NSTEPS  (TDIM / BK)           // 64
#define NSTAGES 4

#define ROWB    80                    // bytes per smem row (64 data + 16 pad)
#define A_BYTES (128 * ROWB)          // 10240
#define B_BYTES (256 * ROWB)          // 20480
#define STAGE_BYTES (A_BYTES + B_BYTES)            // 30720
#define SMEM_BUF 1024                               // means in [0,1024)
#define SMEM_TOTAL (SMEM_BUF + NSTAGES * STAGE_BYTES)   // 123904

__device__ float  g_mean[BATCH * CDIM];
__device__ __half g_xh[(size_t)BATCH * CDIM * TDIM];   // 64 MB fp16 scratch

__device__ __forceinline__ uint32_t smem_u32(const void* p) {
    uint32_t a;
    asm("{ .reg .u64 t; cvta.to.shared.u64 t, %1; cvt.u32.u64 %0, t; }"
        : "=r"(a) : "l"(p));
    return a;
}
__device__ __forceinline__ void cpasync16(uint32_t dst, const void* src) {
    asm volatile("cp.async.cg.shared.global [%0], [%1], 16;"
                 :: "r"(dst), "l"(src) : "memory");
}
__device__ __forceinline__ void ldsm_x4(uint32_t* r, uint32_t addr) {
    asm volatile("ldmatrix.sync.aligned.m8n8.x4.shared.b16 {%0,%1,%2,%3}, [%4];"
                 : "=r"(r[0]), "=r"(r[1]), "=r"(r[2]), "=r"(r[3]) : "r"(addr));
}
__device__ __forceinline__ void mma_f16(float* c, const uint32_t* a,
                                        uint32_t b0, uint32_t b1) {
    asm volatile(
        "mma.sync.aligned.m16n8k16.row.col.f32.f16.f16.f32 "
        "{%0,%1,%2,%3}, {%4,%5,%6,%7}, {%8,%9}, {%0,%1,%2,%3};"
        : "+f"(c[0]), "+f"(c[1]), "+f"(c[2]), "+f"(c[3])
        : "r"(a[0]), "r"(a[1]), "r"(a[2]), "r"(a[3]), "r"(b0), "r"(b1));
}

// ---------------------------------------------------------------------------
// Kernel 1: fused mean + fp16 convert. One warp per (b,c) row.
// ---------------------------------------------------------------------------
__global__ void mean_convert_kernel(const float* __restrict__ X) {
    int warp = (blockIdx.x * blockDim.x + threadIdx.x) >> 5;
    int lane = threadIdx.x & 31;
    if (warp >= BATCH * CDIM) return;

    const float4* row = reinterpret_cast<const float4*>(X + (size_t)warp * TDIM);
    uint2* dst = reinterpret_cast<uint2*>(g_xh + (size_t)warp * TDIM);

    float s = 0.0f;
#pragma unroll
    for (int i = lane; i < TDIM / 4; i += 32) {
        float4 v = row[i];
        s += (v.x + v.y) + (v.z + v.w);
        __half2 h01 = __floats2half2_rn(v.x, v.y);
        __half2 h23 = __floats2half2_rn(v.z, v.w);
        uint2 o;
        o.x = reinterpret_cast<uint32_t&>(h01);
        o.y = reinterpret_cast<uint32_t&>(h23);
        dst[i] = o;
    }
#pragma unroll
    for (int off = 16; off > 0; off >>= 1)
        s += __shfl_xor_sync(0xffffffffu, s, off);
    if (lane == 0) g_mean[warp] = s * (1.0f / TDIM);
}

// ---------------------------------------------------------------------------
// Kernel 2: fp16 HMMA gram. 128 CTAs: blockIdx.x = b*2 + mhalf.
// D[128 x 256] per CTA, 8 warps (2x4), warp tile 64x64, m16n8k16.
// ---------------------------------------------------------------------------
extern __shared__ char dyn_smem[];

__global__ void __launch_bounds__(256)
cov_mma_kernel(float* __restrict__ out) {
    const int b    = blockIdx.x >> 1;
    const int row0 = (blockIdx.x & 1) * 128;
    const int tid  = threadIdx.x;
    const int wid  = tid >> 5;
    const int lane = tid & 31;
    const int g    = lane >> 2;
    const int tig  = lane & 3;
    const int wm   = wid >> 2;         // 0..1
    const int wn   = wid & 3;          // 0..3

    const uint32_t smem_base = smem_u32(dyn_smem);
    float* sm_mean = reinterpret_cast<float*>(dyn_smem);
    sm_mean[tid] = g_mean[b * CDIM + tid];

    // --- loader mapping: 6 x 16B cp.async per thread per stage ---
    const __half* Xb = g_xh + (size_t)b * CDIM * TDIM;
    const char* src[6];
    uint32_t    dstoff[6];
#pragma unroll
    for (int u = 0; u < 6; u++) {
        int idx = tid + u * 256;
        int row, ch;
        uint32_t base;
        int grow;
        if (u < 2) { row = idx >> 2;         ch = idx & 3; base = 0;       grow = row0 + row; }
        else       { row = (idx - 512) >> 2; ch = idx & 3; base = A_BYTES; grow = row; }
        dstoff[u] = base + (uint32_t)(row * ROWB + ch * 16);
        src[u] = reinterpret_cast<const char*>(Xb + (size_t)grow * TDIM + ch * 8);
    }

    // --- prologue: stages 0..2 ---
#pragma unroll
    for (int p = 0; p < NSTAGES - 1; p++) {
        uint32_t sb = smem_base + SMEM_BUF + p * STAGE_BYTES;
#pragma unroll
        for (int u = 0; u < 6; u++)
            cpasync16(sb + dstoff[u], src[u] + (size_t)p * (BK * 2));
        asm volatile("cp.async.commit_group;" ::: "memory");
    }

    // --- per-warp ldmatrix base addresses (within a stage buffer) ---
    // addr(L) = (base_row + (L&15))*ROWB + (L>>4)*16  [+ kk*32]
    uint32_t aoff[4], boff[4];
#pragma unroll
    for (int i = 0; i < 4; i++)
        aoff[i] = (uint32_t)((wm * 64 + i * 16 + (lane & 15)) * ROWB + (lane >> 4) * 16);
#pragma unroll
    for (int jp = 0; jp < 4; jp++)
        boff[jp] = A_BYTES +
                   (uint32_t)((wn * 64 + jp * 16 + (lane & 15)) * ROWB + (lane >> 4) * 16);

    float acc[4][8][4];
#pragma unroll
    for (int i = 0; i < 4; i++)
#pragma unroll
        for (int j = 0; j < 8; j++)
#pragma unroll
            for (int q = 0; q < 4; q++) acc[i][j][q] = 0.0f;

    for (int s = 0; s < NSTEPS; s++) {
        if (s < NSTEPS - (NSTAGES - 1))
            asm volatile("cp.async.wait_group 2;" ::: "memory");
        else
            asm volatile("cp.async.wait_group 0;" ::: "memory");
        __syncthreads();

        const uint32_t st = smem_base + SMEM_BUF + (s & (NSTAGES - 1)) * STAGE_BYTES;

        // prefetch stage s+3 (slot was fully consumed in iteration s-1)
        if (s + NSTAGES - 1 < NSTEPS) {
            const int ps = s + NSTAGES - 1;
            uint32_t sb = smem_base + SMEM_BUF + (ps & (NSTAGES - 1)) * STAGE_BYTES;
#pragma unroll
            for (int u = 0; u < 6; u++)
                cpasync16(sb + dstoff[u], src[u] + (size_t)ps * (BK * 2));
            asm volatile("cp.async.commit_group;" ::: "memory");
        }

#pragma unroll
        for (int kk = 0; kk < 2; kk++) {
            const uint32_t ko = st + kk * 32;       // 16 halves = 32B
            uint32_t a[4][4], br[4][4];
#pragma unroll
            for (int i = 0; i < 4; i++) ldsm_x4(a[i], ko + aoff[i]);
#pragma unroll
            for (int jp = 0; jp < 4; jp++) ldsm_x4(br[jp], ko + boff[jp]);
#pragma unroll
            for (int i = 0; i < 4; i++)
#pragma unroll
                for (int jp = 0; jp < 4; jp++) {
                    mma_f16(acc[i][2 * jp],     a[i], br[jp][0], br[jp][2]);
                    mma_f16(acc[i][2 * jp + 1], a[i], br[jp][1], br[jp][3]);
                }
        }
    }

    // --- epilogue: cov = acc/T - m_r*m_c ---
    const float invT = 1.0f / TDIM;
    float* outB = out + (size_t)b * CDIM * CDIM;

#pragma unroll
    for (int i = 0; i < 4; i++) {
        const int r0 = row0 + wm * 64 + i * 16 + g;
        const int r1 = r0 + 8;
        const float mr0 = sm_mean[r0];
        const float mr1 = sm_mean[r1];
#pragma unroll
        for (int j = 0; j < 8; j++) {
            const int c = wn * 64 + j * 8 + 2 * tig;
            const float mc0 = sm_mean[c];
            const float mc1 = sm_mean[c + 1];
            float2 v0, v1;
            v0.x = acc[i][j][0] * invT - mr0 * mc0;
            v0.y = acc[i][j][1] * invT - mr0 * mc1;
            v1.x = acc[i][j][2] * invT - mr1 * mc0;
            v1.y = acc[i][j][3] * invT - mr1 * mc1;
            *reinterpret_cast<float2*>(outB + (size_t)r0 * CDIM + c) = v0;
            *reinterpret_cast<float2*>(outB + (size_t)r1 * CDIM + c) = v1;
        }
    }
}

// ---------------------------------------------------------------------------
extern "C" void kernel_launch(void* const* d_in, const int* in_sizes, int n_in,
                              void* d_out, int out_size) {
    const float* X = reinterpret_cast<const float*>(d_in[0]);
    float*       O = reinterpret_cast<float*>(d_out);

    cudaFuncSetAttribute(cov_mma_kernel,
                         cudaFuncAttributeMaxDynamicSharedMemorySize,
                         SMEM_TOTAL);

    mean_convert_kernel<<<(BATCH * CDIM * 32) / 256, 256>>>(X);
    cov_mma_kernel<<<BATCH * 2, 256, SMEM_TOTAL>>>(O);
}

// round 7
// speedup vs baseline: 5.1562x; 1.2067x over previous
#include <cuda_runtime.h>
#include <cuda_fp16.h>
#include <cstdint>

#define BATCH 64
#define CDIM  256
#define TDIM  2048

#define THREADS 512
#define BK      64                     // k halves per stage (128 B per row)
#define NSTEPS  (TDIM / BK)            // 32
#define NSTAGES 4

#define ROWB    128                    // swizzled, no pad
#define A_BYTES (128 * ROWB)           // 16384
#define B_BYTES (256 * ROWB)           // 32768
#define STAGE_BYTES (A_BYTES + B_BYTES)              // 49152
#define SMEM_BUF 1024                                 // means in [0,1024)
#define SMEM_TOTAL (SMEM_BUF + NSTAGES * STAGE_BYTES) // 197632

__device__ float  g_mean[BATCH * CDIM];
__device__ __half g_xh[(size_t)BATCH * CDIM * TDIM];  // 64 MB fp16 scratch

__device__ __forceinline__ uint32_t smem_u32(const void* p) {
    uint32_t a;
    asm("{ .reg .u64 t; cvta.to.shared.u64 t, %1; cvt.u32.u64 %0, t; }"
        : "=r"(a) : "l"(p));
    return a;
}
__device__ __forceinline__ void cpasync16(uint32_t dst, const void* src) {
    asm volatile("cp.async.cg.shared.global [%0], [%1], 16;"
                 :: "r"(dst), "l"(src) : "memory");
}
__device__ __forceinline__ void ldsm_x4(uint32_t* r, uint32_t addr) {
    asm volatile("ldmatrix.sync.aligned.m8n8.x4.shared.b16 {%0,%1,%2,%3}, [%4];"
                 : "=r"(r[0]), "=r"(r[1]), "=r"(r[2]), "=r"(r[3]) : "r"(addr));
}
__device__ __forceinline__ void mma_f16(float* c, const uint32_t* a,
                                        uint32_t b0, uint32_t b1) {
    asm volatile(
        "mma.sync.aligned.m16n8k16.row.col.f32.f16.f16.f32 "
        "{%0,%1,%2,%3}, {%4,%5,%6,%7}, {%8,%9}, {%0,%1,%2,%3};"
        : "+f"(c[0]), "+f"(c[1]), "+f"(c[2]), "+f"(c[3])
        : "r"(a[0]), "r"(a[1]), "r"(a[2]), "r"(a[3]), "r"(b0), "r"(b1));
}

// ---------------------------------------------------------------------------
// Kernel 1: fused mean + fp16 convert. One warp per (b,c) row.
// ---------------------------------------------------------------------------
__global__ void mean_convert_kernel(const float* __restrict__ X) {
    int warp = (blockIdx.x * blockDim.x + threadIdx.x) >> 5;
    int lane = threadIdx.x & 31;
    if (warp >= BATCH * CDIM) return;

    const float4* row = reinterpret_cast<const float4*>(X + (size_t)warp * TDIM);
    uint2* dst = reinterpret_cast<uint2*>(g_xh + (size_t)warp * TDIM);

    float s = 0.0f;
#pragma unroll
    for (int i = lane; i < TDIM / 4; i += 32) {
        float4 v = row[i];
        s += (v.x + v.y) + (v.z + v.w);
        __half2 h01 = __floats2half2_rn(v.x, v.y);
        __half2 h23 = __floats2half2_rn(v.z, v.w);
        uint2 o;
        o.x = reinterpret_cast<uint32_t&>(h01);
        o.y = reinterpret_cast<uint32_t&>(h23);
        dst[i] = o;
    }
#pragma unroll
    for (int off = 16; off > 0; off >>= 1)
        s += __shfl_xor_sync(0xffffffffu, s, off);
    if (lane == 0) g_mean[warp] = s * (1.0f / TDIM);
}

// ---------------------------------------------------------------------------
// Kernel 2: fp16 HMMA gram. 128 CTAs: blockIdx.x = b*2 + mhalf.
// D[128 x 256] per CTA, 16 warps (2x8), warp tile 64x32, m16n8k16.
// Smem rows are SW128-XOR swizzled: chunk' = chunk ^ (row & 7).
// ---------------------------------------------------------------------------
extern __shared__ char dyn_smem[];

__global__ void __launch_bounds__(THREADS, 1)
cov_mma_kernel(float* __restrict__ out) {
    const int b    = blockIdx.x >> 1;
    const int row0 = (blockIdx.x & 1) * 128;
    const int tid  = threadIdx.x;
    const int wid  = tid >> 5;
    const int lane = tid & 31;
    const int g    = lane >> 2;
    const int tig  = lane & 3;
    const int wm   = wid >> 3;          // 0..1  (64-row half)
    const int wn   = wid & 7;           // 0..7  (32-col slab)

    const uint32_t smem_base = smem_u32(dyn_smem);
    float* sm_mean = reinterpret_cast<float*>(dyn_smem);
    if (tid < CDIM) sm_mean[tid] = g_mean[b * CDIM + tid];

    // --- loader mapping: 6 x 16B cp.async per thread per stage ---
    // A: 128 rows x 8 chunks (1024 ops), B: 256 rows x 8 chunks (2048 ops)
    const __half* Xb = g_xh + (size_t)b * CDIM * TDIM;
    const char* src[6];
    uint32_t    dstoff[6];
#pragma unroll
    for (int u = 0; u < 6; u++) {
        int idx = tid + u * THREADS;
        int row, ch;
        uint32_t base;
        int grow;
        if (idx < 1024) { row = idx >> 3;          ch = idx & 7; base = 0;       grow = row0 + row; }
        else            { row = (idx - 1024) >> 3; ch = idx & 7; base = A_BYTES; grow = row; }
        dstoff[u] = base + (uint32_t)(row * ROWB + ((ch ^ (row & 7)) << 4));
        src[u] = reinterpret_cast<const char*>(Xb + (size_t)grow * TDIM + ch * 8);
    }

    // --- prologue: stages 0..2 ---
#pragma unroll
    for (int p = 0; p < NSTAGES - 1; p++) {
        uint32_t sb = smem_base + SMEM_BUF + p * STAGE_BYTES;
#pragma unroll
        for (int u = 0; u < 6; u++)
            cpasync16(sb + dstoff[u], src[u] + (size_t)p * (BK * 2));
        asm volatile("cp.async.commit_group;" ::: "memory");
    }

    // --- ldmatrix bases (within stage buffer); chunk selected per kk ---
    const int x  = lane & 7;            // swizzle key (= row & 7 of this lane's row)
    const int hi = lane >> 4;           // 0/1: k-halves 0-7 / 8-15
    uint32_t abase[4], bbase[2];
#pragma unroll
    for (int i = 0; i < 4; i++)
        abase[i] = (uint32_t)((wm * 64 + i * 16 + (lane & 15)) * ROWB);
#pragma unroll
    for (int jp = 0; jp < 2; jp++)
        bbase[jp] = A_BYTES + (uint32_t)((wn * 32 + jp * 16 + (lane & 15)) * ROWB);

    float acc[4][4][4];
#pragma unroll
    for (int i = 0; i < 4; i++)
#pragma unroll
        for (int j = 0; j < 4; j++)
#pragma unroll
            for (int q = 0; q < 4; q++) acc[i][j][q] = 0.0f;

    for (int s = 0; s < NSTEPS; s++) {
        if (s < NSTEPS - (NSTAGES - 1))
            asm volatile("cp.async.wait_group 2;" ::: "memory");
        else
            asm volatile("cp.async.wait_group 0;" ::: "memory");
        __syncthreads();

        const uint32_t st = smem_base + SMEM_BUF + (s & (NSTAGES - 1)) * STAGE_BYTES;

        // prefetch stage s+3 (its slot was consumed before the barrier above)
        if (s + NSTAGES - 1 < NSTEPS) {
            const int ps = s + NSTAGES - 1;
            uint32_t sb = smem_base + SMEM_BUF + (ps & (NSTAGES - 1)) * STAGE_BYTES;
#pragma unroll
            for (int u = 0; u < 6; u++)
                cpasync16(sb + dstoff[u], src[u] + (size_t)ps * (BK * 2));
            asm volatile("cp.async.commit_group;" ::: "memory");
        }

#pragma unroll
        for (int kk = 0; kk < 4; kk++) {
            const uint32_t chsel = (uint32_t)(((2 * kk + hi) ^ x) << 4);
            uint32_t a[4][4], br[2][4];
#pragma unroll
            for (int i = 0; i < 4; i++)  ldsm_x4(a[i],  st + abase[i]  + chsel);
#pragma unroll
            for (int jp = 0; jp < 2; jp++) ldsm_x4(br[jp], st + bbase[jp] + chsel);
#pragma unroll
            for (int i = 0; i < 4; i++)
#pragma unroll
                for (int jp = 0; jp < 2; jp++) {
                    mma_f16(acc[i][2 * jp],     a[i], br[jp][0], br[jp][2]);
                    mma_f16(acc[i][2 * jp + 1], a[i], br[jp][1], br[jp][3]);
                }
        }
    }

    // --- epilogue: cov = acc/T - m_r*m_c ---
    const float invT = 1.0f / TDIM;
    float* outB = out + (size_t)b * CDIM * CDIM;

#pragma unroll
    for (int i = 0; i < 4; i++) {
        const int r0 = row0 + wm * 64 + i * 16 + g;
        const int r1 = r0 + 8;
        const float mr0 = sm_mean[r0];
        const float mr1 = sm_mean[r1];
#pragma unroll
        for (int j = 0; j < 4; j++) {
            const int c = wn * 32 + j * 8 + 2 * tig;
            const float mc0 = sm_mean[c];
            const float mc1 = sm_mean[c + 1];
            float2 v0, v1;
            v0.x = acc[i][j][0] * invT - mr0 * mc0;
            v0.y = acc[i][j][1] * invT - mr0 * mc1;
            v1.x = acc[i][j][2] * invT - mr1 * mc0;
            v1.y = acc[i][j][3] * invT - mr1 * mc1;
            *reinterpret_cast<float2*>(outB + (size_t)r0 * CDIM + c) = v0;
            *reinterpret_cast<float2*>(outB + (size_t)r1 * CDIM + c) = v1;
        }
    }
}

// ---------------------------------------------------------------------------
extern "C" void kernel_launch(void* const* d_in, const int* in_sizes, int n_in,
                              void* d_out, int out_size) {
    const float* X = reinterpret_cast<const float*>(d_in[0]);
    float*       O = reinterpret_cast<float*>(d_out);

    cudaFuncSetAttribute(cov_mma_kernel,
                         cudaFuncAttributeMaxDynamicSharedMemorySize,
                         SMEM_TOTAL);

    mean_convert_kernel<<<(BATCH * CDIM * 32) / 256, 256>>>(X);
    cov_mma_kernel<<<BATCH * 2, THREADS, SMEM_TOTAL>>>(O);
}